// round 7
// baseline (speedup 1.0000x reference)
#include <cuda_runtime.h>
#include <cstdint>

// BinaryLSTM: B=64, T=1024, D=128, H=512, C=2
// R7: xz pre-kernel + K-packed f32x2 recurrence + overlapped cp.async staging.

#define BB   64
#define TT   1024
#define DD   128
#define HH   512
#define G4   2048
#define NCLS 2
#define NCTA 128
#define NTHR 256
#define HROW 516      // h_s row stride (floats): 16B-mult, bb phases 4*bb -> conflict-free
#define WTS  516      // whsT col stride: 16B-mult (q0/q2 2-way conflict hidden by issue)
#define ZROW 20
#define NCOL 16       // gate columns per CTA (4 gates x 4 h-cols)

#define SMEM_FLOATS (BB*HROW + NCOL*WTS + BB*ZROW + 8)
#define SMEM_BYTES  (SMEM_FLOATS * 4)

// xz pre-kernel: 32 tokens x 256 cols per CTA
#define XZ_TOK  32
#define XZ_COLS 256
#define XR      129   // x_s row stride: bank = (tt + d) % 32 -> conflict-free LDS.32
#define XZ_SMEM_FLOATS (XZ_TOK*XR + DD*XZ_COLS)
#define XZ_SMEM_BYTES  (XZ_SMEM_FLOATS * 4)

typedef unsigned long long ull;

// ---- device scratch ----
__device__ float g_h[2][BB][HH];                 // double-buffered hidden state
__device__ float g_hs[(size_t)BB * TT * HH];     // all hidden states [B][T][H]
__device__ float g_xz[(size_t)BB * TT * G4];     // x@Wx + b, layout [(s*BB+b)][G4]
__device__ unsigned g_sub[8 * 32];               // tree barrier sub-counters
__device__ unsigned g_root;
__device__ volatile unsigned g_phase;            // monotonic phase

// ---- PTX helpers ----
__device__ __forceinline__ ull fma2(ull a, ull b, ull c) {
    ull d; asm("fma.rn.f32x2 %0, %1, %2, %3;" : "=l"(d) : "l"(a), "l"(b), "l"(c));
    return d;
}
__device__ __forceinline__ ull dup2(float x) {
    ull d; asm("mov.b64 %0, {%1, %1};" : "=l"(d) : "f"(x)); return d;
}
__device__ __forceinline__ ull pk2(float lo, float hi) {
    ull d; asm("mov.b64 %0, {%1, %2};" : "=l"(d) : "f"(lo), "f"(hi)); return d;
}
__device__ __forceinline__ float hadd2(ull v) {
    float lo, hi; asm("mov.b64 {%0, %1}, %2;" : "=f"(lo), "=f"(hi) : "l"(v));
    return lo + hi;
}
__device__ __forceinline__ uint32_t sa(const void* p) {
    return (uint32_t)__cvta_generic_to_shared(p);
}
__device__ __forceinline__ void cp16(uint32_t s, const void* g) {
    asm volatile("cp.async.cg.shared.global [%0], [%1], 16;" :: "r"(s), "l"(g));
}
#define CP_COMMIT() asm volatile("cp.async.commit_group;" ::: "memory")
#define CP_WAIT1()  asm volatile("cp.async.wait_group 1;" ::: "memory")
#define CP_WAIT0()  asm volatile("cp.async.wait_group 0;" ::: "memory")

// Two-level monotonic grid barrier (128 CTAs: 8 groups x 16). Proven in R6.
__device__ __forceinline__ void grid_barrier(unsigned target, int cta) {
    __threadfence();                       // release
    __syncthreads();
    if (threadIdx.x == 0) {
        unsigned grp = (unsigned)cta & 7u;
        unsigned old = atomicAdd(&g_sub[grp * 32], 1u);
        if ((old & 15u) == 15u) {
            unsigned r = atomicAdd(&g_root, 1u);
            if ((r & 7u) == 7u) g_phase = target;
        }
        while ((int)(g_phase - target) < 0) { }
        __threadfence();                   // acquire
    }
    __syncthreads();
}

__device__ __forceinline__ float fast_sigmoid(float z) {
    return 1.f / (1.f + __expf(-z));
}
__device__ __forceinline__ float fast_tanh(float z) {
    float az = fabsf(z);
    float e  = __expf(-2.f * az);
    float t  = (1.f - e) / (1.f + e);
    return copysignf(t, z);
}

// ---------------------------------------------------------------------------
// Pre-kernel: g_xz[(s*BB+b)*G4 + col] = bias[col] + sum_d x[b,s,d]*Wx[d,col]
// Block = 32 tokens x 256 cols. warp = col-group (broadcast W), lane = token.
// ---------------------------------------------------------------------------
__global__ void __launch_bounds__(NTHR, 1)
xz_kernel(const float* __restrict__ x,
          const float* __restrict__ Wx,
          const float* __restrict__ bias)
{
    extern __shared__ float sm[];
    float* x_s = sm;                  // [XZ_TOK][XR]
    float* w_s = x_s + XZ_TOK * XR;   // [DD][XZ_COLS] stride 256 (broadcast reads)

    const int tid  = threadIdx.x;
    const int tokT = blockIdx.x >> 3;           // 2048 token tiles
    const int colT = blockIdx.x & 7;            // 8 col tiles
    const int cg   = tid >> 5;                  // warp = col group (32 cols)
    const int tt   = tid & 31;                  // lane = token in tile

    // stage x: 32 tokens x 128 floats
    for (int c = tid; c < XZ_TOK * DD; c += NTHR) {
        int t = c >> 7, d = c & (DD - 1);
        int token = tokT * XZ_TOK + t;          // token = s*BB + bb
        int bb = token & (BB - 1), s = token >> 6;
        x_s[t * XR + d] = x[((size_t)bb * TT + s) * DD + d];
    }
    // stage W tile: 128 x 256
    const float* wg = Wx + colT * XZ_COLS;
    for (int c = tid; c < DD * XZ_COLS; c += NTHR) {
        int d = c >> 8, cl = c & 255;
        w_s[c] = wg[(size_t)d * G4 + cl];
    }
    __syncthreads();

    const int c0 = colT * XZ_COLS + cg * 32;    // global col base (32 cols/thread)
    ull acc[16];
    #pragma unroll
    for (int i = 0; i < 16; ++i) acc[i] = *(const ull*)(bias + c0 + 2 * i);

    const float* xr = x_s + tt * XR;
    const float* wr = w_s + cg * 32;
    #pragma unroll 4
    for (int d = 0; d < DD; ++d) {
        ull xd = dup2(xr[d]);
        const ulonglong2* w4 = (const ulonglong2*)(wr + d * XZ_COLS);
        #pragma unroll
        for (int i = 0; i < 8; ++i) {
            ulonglong2 w = w4[i];
            acc[2*i]   = fma2(xd, w.x, acc[2*i]);
            acc[2*i+1] = fma2(xd, w.y, acc[2*i+1]);
        }
    }
    int token = tokT * XZ_TOK + tt;
    ull* outp = (ull*)(g_xz + (size_t)token * G4 + c0);
    #pragma unroll
    for (int i = 0; i < 16; ++i) outp[i] = acc[i];
}

// ---------------------------------------------------------------------------
// Persistent recurrence kernel. CTA owns 4 h-cols (16 gate cols), thread (bb,q)
// computes gate q's 4 columns for batch row bb via K-packed f32x2.
// ---------------------------------------------------------------------------
__global__ void __launch_bounds__(NTHR, 1)
lstm_persistent_kernel(const float* __restrict__ Wh,
                       float* __restrict__ d_cost)
{
    extern __shared__ float sm[];
    float* h_s  = sm;                     // [BB][HROW]
    float* whsT = h_s + BB * HROW;        // [NCOL][WTS]  K-transposed Wh slice
    float* z_s  = whsT + NCOL * WTS;      // [BB][ZROW]
    unsigned* pb = (unsigned*)(z_s + BB * ZROW);

    const int tid = threadIdx.x;
    const int cta = blockIdx.x;
    const int hc0 = cta * 4;

    if (cta == 0 && tid == 0) *d_cost = 0.f;

    // stationary Wh slice, transposed: whsT[cc][k] = Wh[k][gate*HH + hc0 + j]
    for (int i = tid; i < NCOL * HH; i += NTHR) {
        int cc = i >> 9, k = i & (HH - 1);
        whsT[cc * WTS + k] = Wh[(size_t)k * G4 + (cc >> 2) * HH + hc0 + (cc & 3)];
    }
    if (tid == 0) *pb = g_phase;

    const int bb = tid >> 2;
    const int q  = tid & 3;
    __stcg(&g_h[0][bb][hc0 + q], 0.f);
    __syncthreads();
    unsigned bar_t = *pb;

    grid_barrier(++bar_t, cta);           // h0 visible everywhere

    const float* hrow = h_s + bb * HROW;
    const float* w0p = whsT + (4*q + 0) * WTS;
    const float* w1p = whsT + (4*q + 1) * WTS;
    const float* w2p = whsT + (4*q + 2) * WTS;
    const float* w3p = whsT + (4*q + 3) * WTS;
    const size_t xz_base = (size_t)q * HH + hc0;   // + (s*BB+bb)*G4 per step
    const size_t hs_base = ((size_t)bb * TT) * HH + hc0 + q;

    float c_state = 0.f;
    int cur = 0;
    for (int s = 0; s < TT; ++s) {
        // ---- stage h (two k-halves, overlapped with compute) ----
        const char* hg = (const char*)&g_h[cur][0][0];
        for (int c = tid; c < 4096; c += NTHR) {                  // k in [0,256)
            int row = c >> 6, off = (c & 63) << 4;
            cp16(sa(h_s + row * HROW) + (unsigned)off, hg + row * (HH*4) + off);
        }
        CP_COMMIT();
        for (int c = tid; c < 4096; c += NTHR) {                  // k in [256,512)
            int row = c >> 6, off = 1024 + ((c & 63) << 4);
            cp16(sa(h_s + row * HROW) + (unsigned)off, hg + row * (HH*4) + off);
        }
        CP_COMMIT();

        // prefetch xz for this (s, bb, cols 4q..4q+3) while staging flies
        float4 xzv = *(const float4*)(g_xz + ((size_t)s * BB + bb) * G4 + xz_base);

        CP_WAIT1();
        __syncthreads();                  // all threads' half-A done -> h[*][0..255] ready

        ull a0 = pk2(xzv.x, 0.f), a1 = pk2(xzv.y, 0.f);
        ull a2 = pk2(xzv.z, 0.f), a3 = pk2(xzv.w, 0.f);
        #pragma unroll 4
        for (int k = 0; k < 256; k += 8) {
            ulonglong2 ha = *(const ulonglong2*)(hrow + k);
            ulonglong2 hb = *(const ulonglong2*)(hrow + k + 4);
            ulonglong2 wa, wb;
            wa = *(const ulonglong2*)(w0p + k); wb = *(const ulonglong2*)(w0p + k + 4);
            a0 = fma2(ha.x, wa.x, a0); a0 = fma2(ha.y, wa.y, a0);
            a0 = fma2(hb.x, wb.x, a0); a0 = fma2(hb.y, wb.y, a0);
            wa = *(const ulonglong2*)(w1p + k); wb = *(const ulonglong2*)(w1p + k + 4);
            a1 = fma2(ha.x, wa.x, a1); a1 = fma2(ha.y, wa.y, a1);
            a1 = fma2(hb.x, wb.x, a1); a1 = fma2(hb.y, wb.y, a1);
            wa = *(const ulonglong2*)(w2p + k); wb = *(const ulonglong2*)(w2p + k + 4);
            a2 = fma2(ha.x, wa.x, a2); a2 = fma2(ha.y, wa.y, a2);
            a2 = fma2(hb.x, wb.x, a2); a2 = fma2(hb.y, wb.y, a2);
            wa = *(const ulonglong2*)(w3p + k); wb = *(const ulonglong2*)(w3p + k + 4);
            a3 = fma2(ha.x, wa.x, a3); a3 = fma2(ha.y, wa.y, a3);
            a3 = fma2(hb.x, wb.x, a3); a3 = fma2(hb.y, wb.y, a3);
        }
        CP_WAIT0();
        __syncthreads();                  // half-B ready
        #pragma unroll 4
        for (int k = 256; k < 512; k += 8) {
            ulonglong2 ha = *(const ulonglong2*)(hrow + k);
            ulonglong2 hb = *(const ulonglong2*)(hrow + k + 4);
            ulonglong2 wa, wb;
            wa = *(const ulonglong2*)(w0p + k); wb = *(const ulonglong2*)(w0p + k + 4);
            a0 = fma2(ha.x, wa.x, a0); a0 = fma2(ha.y, wa.y, a0);
            a0 = fma2(hb.x, wb.x, a0); a0 = fma2(hb.y, wb.y, a0);
            wa = *(const ulonglong2*)(w1p + k); wb = *(const ulonglong2*)(w1p + k + 4);
            a1 = fma2(ha.x, wa.x, a1); a1 = fma2(ha.y, wa.y, a1);
            a1 = fma2(hb.x, wb.x, a1); a1 = fma2(hb.y, wb.y, a1);
            wa = *(const ulonglong2*)(w2p + k); wb = *(const ulonglong2*)(w2p + k + 4);
            a2 = fma2(ha.x, wa.x, a2); a2 = fma2(ha.y, wa.y, a2);
            a2 = fma2(hb.x, wb.x, a2); a2 = fma2(hb.y, wb.y, a2);
            wa = *(const ulonglong2*)(w3p + k); wb = *(const ulonglong2*)(w3p + k + 4);
            a3 = fma2(ha.x, wa.x, a3); a3 = fma2(ha.y, wa.y, a3);
            a3 = fma2(hb.x, wb.x, a3); a3 = fma2(hb.y, wb.y, a3);
        }
        // horizontal add (even-k lane + odd-k lane) -> z for gate q, cols j=0..3
        *(float4*)(z_s + bb * ZROW + 4 * q) =
            make_float4(hadd2(a0), hadd2(a1), hadd2(a2), hadd2(a3));
        __syncthreads();

        // ---- gates: thread (bb, q) combines i,f,g,o for h-col hc0+q ----
        float zi = z_s[bb * ZROW +      q];
        float zf = z_s[bb * ZROW +  4 + q];
        float zg = z_s[bb * ZROW +  8 + q];
        float zo = z_s[bb * ZROW + 12 + q];
        float ig = fast_sigmoid(zi), fg = fast_sigmoid(zf);
        float gg = fast_tanh(zg),    og = fast_sigmoid(zo);
        c_state  = fg * c_state + ig * gg;
        float hn = og * fast_tanh(c_state);
        __stcg(&g_h[cur ^ 1][bb][hc0 + q], hn);
        g_hs[hs_base + (size_t)s * HH] = hn;

        grid_barrier(++bar_t, cta);
        cur ^= 1;
    }
}

// Head: logits = hs @ Wo + bo (C=2), softmax -> out, mean NLL -> d_cost.
__global__ void __launch_bounds__(256)
head_kernel(const int* __restrict__ labels,
            const float* __restrict__ Wo,
            const float* __restrict__ bo,
            float* __restrict__ out,
            float* __restrict__ d_cost)
{
    __shared__ float part[8];
    int warp = threadIdx.x >> 5, lane = threadIdx.x & 31;
    int bt   = blockIdx.x * 8 + warp;
    const float* hrow = g_hs + (size_t)bt * HH;

    float s0 = 0.f, s1 = 0.f;
    #pragma unroll 4
    for (int k = lane; k < HH; k += 32) {
        float  h = hrow[k];
        float2 w = ((const float2*)Wo)[k];
        s0 += h * w.x; s1 += h * w.y;
    }
    #pragma unroll
    for (int off = 16; off; off >>= 1) {
        s0 += __shfl_xor_sync(0xffffffffu, s0, off);
        s1 += __shfl_xor_sync(0xffffffffu, s1, off);
    }
    if (lane == 0) {
        float l0 = s0 + bo[0], l1 = s1 + bo[1];
        float m  = fmaxf(l0, l1);
        float e0 = __expf(l0 - m), e1 = __expf(l1 - m);
        float Z  = e0 + e1;
        float inv = 1.f / Z;
        ((float2*)out)[bt] = make_float2(e0 * inv, e1 * inv);
        int lab = labels[bt];
        float llab = lab ? l1 : l0;
        part[warp] = -(llab - m - __logf(Z));
    }
    __syncthreads();
    if (threadIdx.x == 0) {
        float sum = 0.f;
        #pragma unroll
        for (int w = 0; w < 8; ++w) sum += part[w];
        atomicAdd(d_cost, sum * (1.f / (float)(BB * TT)));
    }
}

extern "C" void kernel_launch(void* const* d_in, const int* in_sizes, int n_in,
                              void* d_out, int out_size)
{
    (void)in_sizes; (void)n_in; (void)out_size;
    const float* x      = (const float*)d_in[0];
    const int*   labels = (const int*)  d_in[1];
    const float* Wx     = (const float*)d_in[2];
    const float* Wh     = (const float*)d_in[3];
    const float* b      = (const float*)d_in[4];
    const float* Wo     = (const float*)d_in[5];
    const float* bo     = (const float*)d_in[6];
    float* out    = (float*)d_out;
    float* d_cost = out + (size_t)BB * TT * NCLS;

    cudaFuncSetAttribute(xz_kernel,
                         cudaFuncAttributeMaxDynamicSharedMemorySize, XZ_SMEM_BYTES);
    cudaFuncSetAttribute(lstm_persistent_kernel,
                         cudaFuncAttributeMaxDynamicSharedMemorySize, SMEM_BYTES);

    xz_kernel<<<(BB * TT / XZ_TOK) * (G4 / XZ_COLS), NTHR, XZ_SMEM_BYTES>>>(x, Wx, b);
    lstm_persistent_kernel<<<NCTA, NTHR, SMEM_BYTES>>>(Wh, d_cost);
    head_kernel<<<(BB * TT) / 8, 256>>>(labels, Wo, bo, out, d_cost);
}

// round 8
// speedup vs baseline: 1.3337x; 1.3337x over previous
#include <cuda_runtime.h>
#include <cstdint>

// BinaryLSTM: B=64, T=1024, D=128, H=512, C=2
// R8: no h staging (direct L2 __ldcg), thread owns (bb,hc) cell, gates in-register.

#define BB   64
#define TT   1024
#define DD   128
#define HH   512
#define G4   2048
#define NCLS 2
#define NCTA 128
#define NTHR 256
#define WTS  516      // weight stream stride (floats): 16B-mult, conflict-free banks

// xz pre-kernel (unchanged from R7, proven): 32 tokens x 256 cols per CTA
#define XZ_TOK  32
#define XZ_COLS 256
#define XR      129
#define XZ_SMEM_FLOATS (XZ_TOK*XR + DD*XZ_COLS)
#define XZ_SMEM_BYTES  (XZ_SMEM_FLOATS * 4)

typedef unsigned long long ull;

// ---- device scratch ----
__device__ float g_h[2][BB][HH];                 // double-buffered hidden state
__device__ float g_hs[(size_t)BB * TT * HH];     // all hidden states [B][T][H]
__device__ float g_xz[(size_t)BB * TT * G4];     // x@Wx + b, [(s*BB+b)][G4]
__device__ unsigned g_sub[8 * 32];               // tree barrier sub-counters
__device__ unsigned g_root;
__device__ volatile unsigned g_phase;            // monotonic phase

// ---- PTX helpers ----
__device__ __forceinline__ ull fma2(ull a, ull b, ull c) {
    ull d; asm("fma.rn.f32x2 %0, %1, %2, %3;" : "=l"(d) : "l"(a), "l"(b), "l"(c));
    return d;
}
__device__ __forceinline__ ull dup2(float x) {
    ull d; asm("mov.b64 %0, {%1, %1};" : "=l"(d) : "f"(x)); return d;
}
__device__ __forceinline__ ull pk2(float lo, float hi) {
    ull d; asm("mov.b64 %0, {%1, %2};" : "=l"(d) : "f"(lo), "f"(hi)); return d;
}
__device__ __forceinline__ float hadd2(ull v) {
    float lo, hi; asm("mov.b64 {%0, %1}, %2;" : "=f"(lo), "=f"(hi) : "l"(v));
    return lo + hi;
}
__device__ __forceinline__ uint32_t sa(const void* p) {
    return (uint32_t)__cvta_generic_to_shared(p);
}
__device__ __forceinline__ void cp16(uint32_t s, const void* g) {
    asm volatile("cp.async.cg.shared.global [%0], [%1], 16;" :: "r"(s), "l"(g));
}
#define CP_WAITALL() \
    asm volatile("cp.async.commit_group;\ncp.async.wait_group 0;" ::: "memory")

// Two-level monotonic grid barrier (128 CTAs: 8 groups x 16). Proven R6/R7.
__device__ __forceinline__ void grid_barrier(unsigned target, int cta) {
    __threadfence();                       // release
    __syncthreads();
    if (threadIdx.x == 0) {
        unsigned grp = (unsigned)cta & 7u;
        unsigned old = atomicAdd(&g_sub[grp * 32], 1u);
        if ((old & 15u) == 15u) {
            unsigned r = atomicAdd(&g_root, 1u);
            if ((r & 7u) == 7u) g_phase = target;
        }
        while ((int)(g_phase - target) < 0) { }
        __threadfence();                   // acquire
    }
    __syncthreads();
}

__device__ __forceinline__ float fast_sigmoid(float z) {
    return 1.f / (1.f + __expf(-z));
}
__device__ __forceinline__ float fast_tanh(float z) {
    float az = fabsf(z);
    float e  = __expf(-2.f * az);
    float t  = (1.f - e) / (1.f + e);
    return copysignf(t, z);
}

// ---------------------------------------------------------------------------
// Pre-kernel (verbatim from R7, proven): g_xz[token][col] = b[col] + x.Wx
// ---------------------------------------------------------------------------
__global__ void __launch_bounds__(NTHR, 1)
xz_kernel(const float* __restrict__ x,
          const float* __restrict__ Wx,
          const float* __restrict__ bias)
{
    extern __shared__ float sm[];
    float* x_s = sm;                  // [XZ_TOK][XR]
    float* w_s = x_s + XZ_TOK * XR;   // [DD][XZ_COLS]

    const int tid  = threadIdx.x;
    const int tokT = blockIdx.x >> 3;
    const int colT = blockIdx.x & 7;
    const int cg   = tid >> 5;
    const int tt   = tid & 31;

    for (int c = tid; c < XZ_TOK * DD; c += NTHR) {
        int t = c >> 7, d = c & (DD - 1);
        int token = tokT * XZ_TOK + t;          // token = s*BB + bb
        int bb = token & (BB - 1), s = token >> 6;
        x_s[t * XR + d] = x[((size_t)bb * TT + s) * DD + d];
    }
    const float* wg = Wx + colT * XZ_COLS;
    for (int c = tid; c < DD * XZ_COLS; c += NTHR) {
        int d = c >> 8, cl = c & 255;
        w_s[c] = wg[(size_t)d * G4 + cl];
    }
    __syncthreads();

    const int c0 = colT * XZ_COLS + cg * 32;
    ull acc[16];
    #pragma unroll
    for (int i = 0; i < 16; ++i) acc[i] = *(const ull*)(bias + c0 + 2 * i);

    const float* xr = x_s + tt * XR;
    const float* wr = w_s + cg * 32;
    #pragma unroll 4
    for (int d = 0; d < DD; ++d) {
        ull xd = dup2(xr[d]);
        const ulonglong2* w4 = (const ulonglong2*)(wr + d * XZ_COLS);
        #pragma unroll
        for (int i = 0; i < 8; ++i) {
            ulonglong2 w = w4[i];
            acc[2*i]   = fma2(xd, w.x, acc[2*i]);
            acc[2*i+1] = fma2(xd, w.y, acc[2*i+1]);
        }
    }
    int token = tokT * XZ_TOK + tt;
    ull* outp = (ull*)(g_xz + (size_t)token * G4 + c0);
    #pragma unroll
    for (int i = 0; i < 16; ++i) outp[i] = acc[i];
}

// ---------------------------------------------------------------------------
// Recurrence: 128 CTAs x 4 h-cols. Thread (bb = tid>>2, j = tid&3) owns cell
// (bb, hc = cta*4+j): computes all 4 gate dots over k via f32x2, h read
// directly from L2. 16 weight streams in smem, conflict-free.
// ---------------------------------------------------------------------------
__global__ void __launch_bounds__(NTHR, 1)
lstm_persistent_kernel(const float* __restrict__ Wh,
                       float* __restrict__ d_cost)
{
    __shared__ float whsT[16 * WTS];      // stream cc = g*4+j: Wh[k][g*HH+cta*4+j]
    __shared__ unsigned pb_s;

    const int tid = threadIdx.x;
    const int cta = blockIdx.x;
    const int bb  = tid >> 2;
    const int j   = tid & 3;
    const int hc  = cta * 4 + j;

    if (cta == 0 && tid == 0) *d_cost = 0.f;

    // one-time: stationary K-major weight slice (16 streams x 512)
    for (int i = tid; i < 16 * HH; i += NTHR) {
        int cc = i >> 9, k = i & (HH - 1);
        int g = cc >> 2, jj = cc & 3;
        whsT[cc * WTS + k] = Wh[(size_t)k * G4 + g * HH + cta * 4 + jj];
    }
    if (tid == 0) pb_s = g_phase;
    __stcg(&g_h[0][bb][hc], 0.f);
    __syncthreads();
    unsigned bar_t = pb_s;

    grid_barrier(++bar_t, cta);           // h0 + weights visible / loaded

    const float* w0 = whsT + (0 * 4 + j) * WTS;
    const float* w1 = whsT + (1 * 4 + j) * WTS;
    const float* w2 = whsT + (2 * 4 + j) * WTS;
    const float* w3 = whsT + (3 * 4 + j) * WTS;
    const size_t hs_base = (size_t)bb * TT * HH + hc;
    const size_t xz_off  = (size_t)cta * 4 + j;

    float c_state = 0.f;
    int cur = 0;
    for (int s = 0; s < TT; ++s) {
        // xz pre-activations for this cell's 4 gates (L2/DRAM, prefetch early)
        const float* xzp = g_xz + ((size_t)s * BB + bb) * G4 + xz_off;
        float xzi = __ldcg(xzp);
        float xzf = __ldcg(xzp + HH);
        float xzg = __ldcg(xzp + 2 * HH);
        float xzo = __ldcg(xzp + 3 * HH);

        ull a0 = pk2(xzi, 0.f), a1 = pk2(xzf, 0.f);
        ull a2 = pk2(xzg, 0.f), a3 = pk2(xzo, 0.f);

        // h row for this bb, straight from L2 (all CTAs read the same 128KB)
        const float* hr = &g_h[cur][bb][0];
        #pragma unroll 4
        for (int k = 0; k < HH; k += 8) {
            double2 hA = __ldcg((const double2*)(hr + k));
            double2 hB = __ldcg((const double2*)(hr + k + 4));
            ull hx = __double_as_longlong(hA.x);
            ull hy = __double_as_longlong(hA.y);
            ull hz = __double_as_longlong(hB.x);
            ull hw = __double_as_longlong(hB.y);
            ulonglong2 wa, wb;
            wa = *(const ulonglong2*)(w0 + k); wb = *(const ulonglong2*)(w0 + k + 4);
            a0 = fma2(hx, wa.x, a0); a0 = fma2(hy, wa.y, a0);
            a0 = fma2(hz, wb.x, a0); a0 = fma2(hw, wb.y, a0);
            wa = *(const ulonglong2*)(w1 + k); wb = *(const ulonglong2*)(w1 + k + 4);
            a1 = fma2(hx, wa.x, a1); a1 = fma2(hy, wa.y, a1);
            a1 = fma2(hz, wb.x, a1); a1 = fma2(hw, wb.y, a1);
            wa = *(const ulonglong2*)(w2 + k); wb = *(const ulonglong2*)(w2 + k + 4);
            a2 = fma2(hx, wa.x, a2); a2 = fma2(hy, wa.y, a2);
            a2 = fma2(hz, wb.x, a2); a2 = fma2(hw, wb.y, a2);
            wa = *(const ulonglong2*)(w3 + k); wb = *(const ulonglong2*)(w3 + k + 4);
            a3 = fma2(hx, wa.x, a3); a3 = fma2(hy, wa.y, a3);
            a3 = fma2(hz, wb.x, a3); a3 = fma2(hw, wb.y, a3);
        }

        float zi = hadd2(a0), zf = hadd2(a1), zg = hadd2(a2), zo = hadd2(a3);
        float ig = fast_sigmoid(zi), fg = fast_sigmoid(zf);
        float gg = fast_tanh(zg),    og = fast_sigmoid(zo);
        c_state  = fg * c_state + ig * gg;
        float hn = og * fast_tanh(c_state);
        __stcg(&g_h[cur ^ 1][bb][hc], hn);
        g_hs[hs_base + (size_t)s * HH] = hn;

        grid_barrier(++bar_t, cta);
        cur ^= 1;
    }
}

// Head: logits = hs @ Wo + bo (C=2), softmax -> out, mean NLL -> d_cost.
__global__ void __launch_bounds__(256)
head_kernel(const int* __restrict__ labels,
            const float* __restrict__ Wo,
            const float* __restrict__ bo,
            float* __restrict__ out,
            float* __restrict__ d_cost)
{
    __shared__ float part[8];
    int warp = threadIdx.x >> 5, lane = threadIdx.x & 31;
    int bt   = blockIdx.x * 8 + warp;
    const float* hrow = g_hs + (size_t)bt * HH;

    float s0 = 0.f, s1 = 0.f;
    #pragma unroll 4
    for (int k = lane; k < HH; k += 32) {
        float  h = hrow[k];
        float2 w = ((const float2*)Wo)[k];
        s0 += h * w.x; s1 += h * w.y;
    }
    #pragma unroll
    for (int off = 16; off; off >>= 1) {
        s0 += __shfl_xor_sync(0xffffffffu, s0, off);
        s1 += __shfl_xor_sync(0xffffffffu, s1, off);
    }
    if (lane == 0) {
        float l0 = s0 + bo[0], l1 = s1 + bo[1];
        float m  = fmaxf(l0, l1);
        float e0 = __expf(l0 - m), e1 = __expf(l1 - m);
        float Z  = e0 + e1;
        float inv = 1.f / Z;
        ((float2*)out)[bt] = make_float2(e0 * inv, e1 * inv);
        int lab = labels[bt];
        float llab = lab ? l1 : l0;
        part[warp] = -(llab - m - __logf(Z));
    }
    __syncthreads();
    if (threadIdx.x == 0) {
        float sum = 0.f;
        #pragma unroll
        for (int w = 0; w < 8; ++w) sum += part[w];
        atomicAdd(d_cost, sum * (1.f / (float)(BB * TT)));
    }
}

extern "C" void kernel_launch(void* const* d_in, const int* in_sizes, int n_in,
                              void* d_out, int out_size)
{
    (void)in_sizes; (void)n_in; (void)out_size;
    const float* x      = (const float*)d_in[0];
    const int*   labels = (const int*)  d_in[1];
    const float* Wx     = (const float*)d_in[2];
    const float* Wh     = (const float*)d_in[3];
    const float* b      = (const float*)d_in[4];
    const float* Wo     = (const float*)d_in[5];
    const float* bo     = (const float*)d_in[6];
    float* out    = (float*)d_out;
    float* d_cost = out + (size_t)BB * TT * NCLS;

    cudaFuncSetAttribute(xz_kernel,
                         cudaFuncAttributeMaxDynamicSharedMemorySize, XZ_SMEM_BYTES);

    xz_kernel<<<(BB * TT / XZ_TOK) * (G4 / XZ_COLS), NTHR, XZ_SMEM_BYTES>>>(x, Wx, b);
    lstm_persistent_kernel<<<NCTA, NTHR>>>(Wh, d_cost);
    head_kernel<<<(BB * TT) / 8, 256>>>(labels, Wo, bo, out, d_cost);
}

// round 9
// speedup vs baseline: 1.4430x; 1.0820x over previous
#include <cuda_runtime.h>
#include <cstdint>

// BinaryLSTM: B=64, T=1024, D=128, H=512, C=2
// R9: GPU-scope acq/rel barrier (no volatile/SYS, no per-thread MEMBAR)
//     + R8 cell-per-thread mapping + all-smem inner loop (cp.async h staging).

#define BB   64
#define TT   1024
#define DD   128
#define HH   512
#define G4   2048
#define NCLS 2
#define NCTA 128
#define NTHR 256
#define HROW 516      // h_s row stride (floats): 16B-mult, conflict-free
#define WTS  516      // weight stream stride

#define SMEM_FLOATS (BB*HROW + 16*WTS + 8)
#define SMEM_BYTES  (SMEM_FLOATS * 4)

// xz pre-kernel (proven): 32 tokens x 256 cols per CTA
#define XZ_TOK  32
#define XZ_COLS 256
#define XR      129
#define XZ_SMEM_FLOATS (XZ_TOK*XR + DD*XZ_COLS)
#define XZ_SMEM_BYTES  (XZ_SMEM_FLOATS * 4)

typedef unsigned long long ull;

// ---- device scratch ----
__device__ float g_h[2][BB][HH];
__device__ float g_hs[(size_t)BB * TT * HH];
__device__ float g_xz[(size_t)BB * TT * G4];
__device__ unsigned g_sub[8 * 32];               // tree barrier sub-counters
__device__ unsigned g_root;
__device__ unsigned g_phase;                     // monotonic phase (NOT volatile)

// ---- PTX helpers ----
__device__ __forceinline__ ull fma2(ull a, ull b, ull c) {
    ull d; asm("fma.rn.f32x2 %0, %1, %2, %3;" : "=l"(d) : "l"(a), "l"(b), "l"(c));
    return d;
}
__device__ __forceinline__ ull dup2(float x) {
    ull d; asm("mov.b64 %0, {%1, %1};" : "=l"(d) : "f"(x)); return d;
}
__device__ __forceinline__ ull pk2(float lo, float hi) {
    ull d; asm("mov.b64 %0, {%1, %2};" : "=l"(d) : "f"(lo), "f"(hi)); return d;
}
__device__ __forceinline__ float hadd2(ull v) {
    float lo, hi; asm("mov.b64 {%0, %1}, %2;" : "=f"(lo), "=f"(hi) : "l"(v));
    return lo + hi;
}
__device__ __forceinline__ uint32_t sa(const void* p) {
    return (uint32_t)__cvta_generic_to_shared(p);
}
__device__ __forceinline__ void cp16(uint32_t s, const void* g) {
    asm volatile("cp.async.cg.shared.global [%0], [%1], 16;" :: "r"(s), "l"(g));
}
#define CP_WAITALL() \
    asm volatile("cp.async.commit_group;\ncp.async.wait_group 0;" ::: "memory")

// GPU-scope sync ops (explicitly .gpu — NOT sys-scope volatile)
__device__ __forceinline__ unsigned atom_add_acqrel_gpu(unsigned* p, unsigned v) {
    unsigned old;
    asm volatile("atom.add.acq_rel.gpu.global.u32 %0, [%1], %2;"
                 : "=r"(old) : "l"(p), "r"(v) : "memory");
    return old;
}
__device__ __forceinline__ void st_release_gpu(unsigned* p, unsigned v) {
    asm volatile("st.release.gpu.global.u32 [%0], %1;" :: "l"(p), "r"(v) : "memory");
}
__device__ __forceinline__ unsigned ld_acquire_gpu(const unsigned* p) {
    unsigned v;
    asm volatile("ld.acquire.gpu.global.u32 %0, [%1];" : "=r"(v) : "l"(p) : "memory");
    return v;
}

// Two-level monotonic grid barrier, CG-style: bar.sync gives intra-CTA HB, the
// elected acq_rel arrive carries all threads' prior stores; acquire-poll +
// bar.sync publishes to consumers. No MEMBAR.GPU, no SYS scope anywhere.
__device__ __forceinline__ void grid_barrier(unsigned target, int cta) {
    __syncthreads();                       // all threads' h stores HB the arrive
    if (threadIdx.x == 0) {
        unsigned grp = (unsigned)cta & 7u;
        unsigned old = atom_add_acqrel_gpu(&g_sub[grp * 32], 1u);
        if ((old & 15u) == 15u) {
            unsigned r = atom_add_acqrel_gpu(&g_root, 1u);
            if ((r & 7u) == 7u) st_release_gpu(&g_phase, target);
        }
        while ((int)(ld_acquire_gpu(&g_phase) - target) < 0) { }
    }
    __syncthreads();                       // publish to all threads
}

__device__ __forceinline__ float fast_sigmoid(float z) {
    return 1.f / (1.f + __expf(-z));
}
__device__ __forceinline__ float fast_tanh(float z) {
    float az = fabsf(z);
    float e  = __expf(-2.f * az);
    float t  = (1.f - e) / (1.f + e);
    return copysignf(t, z);
}

// ---------------------------------------------------------------------------
// Pre-kernel (verbatim, proven): g_xz[token][col] = b[col] + x.Wx
// ---------------------------------------------------------------------------
__global__ void __launch_bounds__(NTHR, 1)
xz_kernel(const float* __restrict__ x,
          const float* __restrict__ Wx,
          const float* __restrict__ bias)
{
    extern __shared__ float sm[];
    float* x_s = sm;                  // [XZ_TOK][XR]
    float* w_s = x_s + XZ_TOK * XR;   // [DD][XZ_COLS]

    const int tid  = threadIdx.x;
    const int tokT = blockIdx.x >> 3;
    const int colT = blockIdx.x & 7;
    const int cg   = tid >> 5;
    const int tt   = tid & 31;

    for (int c = tid; c < XZ_TOK * DD; c += NTHR) {
        int t = c >> 7, d = c & (DD - 1);
        int token = tokT * XZ_TOK + t;          // token = s*BB + bb
        int bb = token & (BB - 1), s = token >> 6;
        x_s[t * XR + d] = x[((size_t)bb * TT + s) * DD + d];
    }
    const float* wg = Wx + colT * XZ_COLS;
    for (int c = tid; c < DD * XZ_COLS; c += NTHR) {
        int d = c >> 8, cl = c & 255;
        w_s[c] = wg[(size_t)d * G4 + cl];
    }
    __syncthreads();

    const int c0 = colT * XZ_COLS + cg * 32;
    ull acc[16];
    #pragma unroll
    for (int i = 0; i < 16; ++i) acc[i] = *(const ull*)(bias + c0 + 2 * i);

    const float* xr = x_s + tt * XR;
    const float* wr = w_s + cg * 32;
    #pragma unroll 4
    for (int d = 0; d < DD; ++d) {
        ull xd = dup2(xr[d]);
        const ulonglong2* w4 = (const ulonglong2*)(wr + d * XZ_COLS);
        #pragma unroll
        for (int i = 0; i < 8; ++i) {
            ulonglong2 w = w4[i];
            acc[2*i]   = fma2(xd, w.x, acc[2*i]);
            acc[2*i+1] = fma2(xd, w.y, acc[2*i+1]);
        }
    }
    int token = tokT * XZ_TOK + tt;
    ull* outp = (ull*)(g_xz + (size_t)token * G4 + c0);
    #pragma unroll
    for (int i = 0; i < 16; ++i) outp[i] = acc[i];
}

// ---------------------------------------------------------------------------
// Recurrence: thread (bb = tid>>2, j = tid&3) owns cell (bb, hc = cta*4+j).
// h staged to smem via cp.async; all-smem inner loop; gates in-register.
// ---------------------------------------------------------------------------
__global__ void __launch_bounds__(NTHR, 1)
lstm_persistent_kernel(const float* __restrict__ Wh,
                       float* __restrict__ d_cost)
{
    extern __shared__ float sm[];
    float* h_s  = sm;                 // [BB][HROW]
    float* whsT = h_s + BB * HROW;    // [16][WTS]  stream cc=g*4+j
    unsigned* pb = (unsigned*)(whsT + 16 * WTS);

    const int tid = threadIdx.x;
    const int cta = blockIdx.x;
    const int bb  = tid >> 2;
    const int j   = tid & 3;
    const int hc  = cta * 4 + j;

    if (cta == 0 && tid == 0) *d_cost = 0.f;

    // stationary K-major weight slice (16 streams x 512)
    for (int i = tid; i < 16 * HH; i += NTHR) {
        int cc = i >> 9, k = i & (HH - 1);
        int g = cc >> 2, jj = cc & 3;
        whsT[cc * WTS + k] = Wh[(size_t)k * G4 + g * HH + cta * 4 + jj];
    }
    if (tid == 0) *pb = ld_acquire_gpu(&g_phase);
    __stcg(&g_h[0][bb][hc], 0.f);
    __syncthreads();
    unsigned bar_t = *pb;

    grid_barrier(++bar_t, cta);           // h0 visible everywhere

    const float* hr = h_s + bb * HROW;
    const float* w0 = whsT + (0 * 4 + j) * WTS;
    const float* w1 = whsT + (1 * 4 + j) * WTS;
    const float* w2 = whsT + (2 * 4 + j) * WTS;
    const float* w3 = whsT + (3 * 4 + j) * WTS;
    const size_t hs_base = (size_t)bb * TT * HH + hc;
    const size_t xz_off  = (size_t)cta * 4 + j;

    float c_state = 0.f;
    int cur = 0;
    for (int s = 0; s < TT; ++s) {
        // stage h -> smem (async, 32 chunks/thread, perfectly coalesced)
        const char* hg = (const char*)&g_h[cur][0][0];
        #pragma unroll
        for (int c = tid; c < 8192; c += NTHR) {
            int row = c >> 7, off = (c & 127) << 4;
            cp16(sa(h_s + row * HROW) + (unsigned)off, hg + row * (HH * 4) + off);
        }
        // xz pre-activations for this cell's 4 gates (overlaps staging)
        const float* xzp = g_xz + ((size_t)s * BB + bb) * G4 + xz_off;
        float xzi = __ldcg(xzp);
        float xzf = __ldcg(xzp + HH);
        float xzg = __ldcg(xzp + 2 * HH);
        float xzo = __ldcg(xzp + 3 * HH);
        CP_WAITALL();
        __syncthreads();

        ull a0 = pk2(xzi, 0.f), a1 = pk2(xzf, 0.f);
        ull a2 = pk2(xzg, 0.f), a3 = pk2(xzo, 0.f);

        #pragma unroll 4
        for (int k = 0; k < HH; k += 8) {
            ulonglong2 hA = *(const ulonglong2*)(hr + k);
            ulonglong2 hB = *(const ulonglong2*)(hr + k + 4);
            ulonglong2 wa, wb;
            wa = *(const ulonglong2*)(w0 + k); wb = *(const ulonglong2*)(w0 + k + 4);
            a0 = fma2(hA.x, wa.x, a0); a0 = fma2(hA.y, wa.y, a0);
            a0 = fma2(hB.x, wb.x, a0); a0 = fma2(hB.y, wb.y, a0);
            wa = *(const ulonglong2*)(w1 + k); wb = *(const ulonglong2*)(w1 + k + 4);
            a1 = fma2(hA.x, wa.x, a1); a1 = fma2(hA.y, wa.y, a1);
            a1 = fma2(hB.x, wb.x, a1); a1 = fma2(hB.y, wb.y, a1);
            wa = *(const ulonglong2*)(w2 + k); wb = *(const ulonglong2*)(w2 + k + 4);
            a2 = fma2(hA.x, wa.x, a2); a2 = fma2(hA.y, wa.y, a2);
            a2 = fma2(hB.x, wb.x, a2); a2 = fma2(hB.y, wb.y, a2);
            wa = *(const ulonglong2*)(w3 + k); wb = *(const ulonglong2*)(w3 + k + 4);
            a3 = fma2(hA.x, wa.x, a3); a3 = fma2(hA.y, wa.y, a3);
            a3 = fma2(hB.x, wb.x, a3); a3 = fma2(hB.y, wb.y, a3);
        }

        float zi = hadd2(a0), zf = hadd2(a1), zg = hadd2(a2), zo = hadd2(a3);
        float ig = fast_sigmoid(zi), fg = fast_sigmoid(zf);
        float gg = fast_tanh(zg),    og = fast_sigmoid(zo);
        c_state  = fg * c_state + ig * gg;
        float hn = og * fast_tanh(c_state);
        __stcg(&g_h[cur ^ 1][bb][hc], hn);
        g_hs[hs_base + (size_t)s * HH] = hn;

        grid_barrier(++bar_t, cta);
        cur ^= 1;
    }
}

// Head: logits = hs @ Wo + bo (C=2), softmax -> out, mean NLL -> d_cost.
__global__ void __launch_bounds__(256)
head_kernel(const int* __restrict__ labels,
            const float* __restrict__ Wo,
            const float* __restrict__ bo,
            float* __restrict__ out,
            float* __restrict__ d_cost)
{
    __shared__ float part[8];
    int warp = threadIdx.x >> 5, lane = threadIdx.x & 31;
    int bt   = blockIdx.x * 8 + warp;
    const float* hrow = g_hs + (size_t)bt * HH;

    float s0 = 0.f, s1 = 0.f;
    #pragma unroll 4
    for (int k = lane; k < HH; k += 32) {
        float  h = hrow[k];
        float2 w = ((const float2*)Wo)[k];
        s0 += h * w.x; s1 += h * w.y;
    }
    #pragma unroll
    for (int off = 16; off; off >>= 1) {
        s0 += __shfl_xor_sync(0xffffffffu, s0, off);
        s1 += __shfl_xor_sync(0xffffffffu, s1, off);
    }
    if (lane == 0) {
        float l0 = s0 + bo[0], l1 = s1 + bo[1];
        float m  = fmaxf(l0, l1);
        float e0 = __expf(l0 - m), e1 = __expf(l1 - m);
        float Z  = e0 + e1;
        float inv = 1.f / Z;
        ((float2*)out)[bt] = make_float2(e0 * inv, e1 * inv);
        int lab = labels[bt];
        float llab = lab ? l1 : l0;
        part[warp] = -(llab - m - __logf(Z));
    }
    __syncthreads();
    if (threadIdx.x == 0) {
        float sum = 0.f;
        #pragma unroll
        for (int w = 0; w < 8; ++w) sum += part[w];
        atomicAdd(d_cost, sum * (1.f / (float)(BB * TT)));
    }
}

extern "C" void kernel_launch(void* const* d_in, const int* in_sizes, int n_in,
                              void* d_out, int out_size)
{
    (void)in_sizes; (void)n_in; (void)out_size;
    const float* x      = (const float*)d_in[0];
    const int*   labels = (const int*)  d_in[1];
    const float* Wx     = (const float*)d_in[2];
    const float* Wh     = (const float*)d_in[3];
    const float* b      = (const float*)d_in[4];
    const float* Wo     = (const float*)d_in[5];
    const float* bo     = (const float*)d_in[6];
    float* out    = (float*)d_out;
    float* d_cost = out + (size_t)BB * TT * NCLS;

    cudaFuncSetAttribute(xz_kernel,
                         cudaFuncAttributeMaxDynamicSharedMemorySize, XZ_SMEM_BYTES);
    cudaFuncSetAttribute(lstm_persistent_kernel,
                         cudaFuncAttributeMaxDynamicSharedMemorySize, SMEM_BYTES);

    xz_kernel<<<(BB * TT / XZ_TOK) * (G4 / XZ_COLS), NTHR, XZ_SMEM_BYTES>>>(x, Wx, b);
    lstm_persistent_kernel<<<NCTA, NTHR, SMEM_BYTES>>>(Wh, d_cost);
    head_kernel<<<(BB * TT) / 8, 256>>>(labels, Wo, bo, out, d_cost);
}